// round 16
// baseline (speedup 1.0000x reference)
#include <cuda_runtime.h>
#include <cuda_bf16.h>

#define NPTS  16384
#define NNBR  32
#define CIN   16
#define COUT  16
#define NB    16
#define GAMMA 10.0f
#define EPSF  1e-12f

// Scratch (allocation-free rule: __device__ globals)
__device__ float4     g_inputT[NPTS * 4];   // [n*4+q] : channels 4q..4q+3 of point n
__device__ float4     g_coords4[NPTS];      // padded coords
__device__ ulonglong2 g_Wt4[1024];          // W tiled for 8-role epilogue:
// gi = o*64 + r*8 + bb*2 + hp   (r = tb*2+tc)
//  w.x = (W[o][8tc+4hp+0][4tb+bb], W[o][8tc+4hp+1][4tb+bb])
//  w.y = (W[o][8tc+4hp+2][4tb+bb], W[o][8tc+4hp+3][4tb+bb])

// ---------------- f32x2 / fast-math helpers (sm_103a) ----------------------
__device__ __forceinline__ unsigned long long ffma2(unsigned long long a,
                                                    unsigned long long b,
                                                    unsigned long long c) {
    unsigned long long d;
    asm("fma.rn.f32x2 %0, %1, %2, %3;" : "=l"(d) : "l"(a), "l"(b), "l"(c));
    return d;
}
__device__ __forceinline__ unsigned long long dup2(float x) {
    unsigned long long d;
    asm("mov.b64 %0, {%1, %1};" : "=l"(d) : "f"(x));
    return d;
}
__device__ __forceinline__ unsigned long long pack2(float lo, float hi) {
    unsigned long long d;
    asm("mov.b64 %0, {%1, %2};" : "=l"(d) : "f"(lo), "f"(hi));
    return d;
}
__device__ __forceinline__ float2 unpack2(unsigned long long v) {
    float2 f;
    asm("mov.b64 {%0, %1}, %2;" : "=f"(f.x), "=f"(f.y) : "l"(v));
    return f;
}
__device__ __forceinline__ float ex2(float x) {
    float y;
    asm("ex2.approx.ftz.f32 %0, %1;" : "=f"(y) : "f"(x));
    return y;
}
__device__ __forceinline__ float lg2(float x) {
    float y;
    asm("lg2.approx.ftz.f32 %0, %1;" : "=f"(y) : "f"(x));
    return y;
}
__device__ __forceinline__ float sqrt_approx(float x) {
    float y;
    asm("sqrt.approx.ftz.f32 %0, %1;" : "=f"(y) : "f"(x));
    return y;
}

// ---------------------------------------------------------------------------
// Prep: transpose input (C,N)->(N,C) float4 rows (2 pts/thread), pad coords,
// build the 8-role-tiled W table.
// ---------------------------------------------------------------------------
__global__ void prep_kernel(const float* __restrict__ input,
                            const float* __restrict__ coords,
                            const float* __restrict__ W) {
    const int idx = blockIdx.x * blockDim.x + threadIdx.x;   // 0 .. 32767
    const int q  = idx >> 13;           // 0..3 channel quartet
    const int n0 = (idx & 8191) * 2;    // even point index

    const float2* in2 = (const float2*)input;
    const float2 v0 = in2[((4 * q + 0) * NPTS + n0) >> 1];
    const float2 v1 = in2[((4 * q + 1) * NPTS + n0) >> 1];
    const float2 v2 = in2[((4 * q + 2) * NPTS + n0) >> 1];
    const float2 v3 = in2[((4 * q + 3) * NPTS + n0) >> 1];
    g_inputT[(n0 + 0) * 4 + q] = make_float4(v0.x, v1.x, v2.x, v3.x);
    g_inputT[(n0 + 1) * 4 + q] = make_float4(v0.y, v1.y, v2.y, v3.y);

    if (q == 0) {
        const float2* co2 = (const float2*)(coords + 3 * n0);   // 6 floats
        const float2 a = co2[0], b = co2[1], c = co2[2];
        g_coords4[n0 + 0] = make_float4(a.x, a.y, b.x, 0.0f);
        g_coords4[n0 + 1] = make_float4(b.y, c.x, c.y, 0.0f);
    }
    if (idx < 1024) {
        const int o  = idx >> 6;
        const int r  = (idx >> 3) & 7;
        const int bb = (idx >> 1) & 3;
        const int hp = idx & 1;
        const int tb = r >> 1, tc = r & 1;
        const int b  = 4 * tb + bb;
        ulonglong2 w2;
        w2.x = pack2(W[(o * 16 + 8 * tc + 4 * hp + 0) * 16 + b],
                     W[(o * 16 + 8 * tc + 4 * hp + 1) * 16 + b]);
        w2.y = pack2(W[(o * 16 + 8 * tc + 4 * hp + 2) * 16 + b],
                     W[(o * 16 + 8 * tc + 4 * hp + 3) * 16 + b]);
        g_Wt4[idx] = w2;
    }
}

// ---------------------------------------------------------------------------
// Main: 8 lanes/point, role (tb,tc): bases 4tb..4tb+3 x channels 8tc..8tc+7.
// acc2[bb][cp] (f32x2, 16 u64 = 32 regs -> occupancy 2x vs R15).
// Per neighbor per lane: 2 LDG.128 (own channel octet; tc-chunks merge into
// the same L1 lines per instr -> wavefronts unchanged vs R15), 4 ex2 (2x
// redundancy total), 16 FFMA2. No mainloop SHFL/LDS/STS.
// Epilogue: role-tiled W in smem, pad-9 stride => roles on distinct bank
// quartets (conflict-free LDS.128); width-8 butterfly; lane l -> outputs 2l,2l+1.
// ---------------------------------------------------------------------------
__global__ __launch_bounds__(256, 4)
void conv_kernel(const float* __restrict__ centers,
                 const float* __restrict__ mask,
                 const int*   __restrict__ neighbors,
                 float*       __restrict__ out) {
    __shared__ ulonglong2 smW[1152];   // 128 groups x 9 (pad) = 18432 B

    const int tid = threadIdx.x;
    #pragma unroll
    for (int e = 0; e < 4; e++) {
        const int gi = tid + 256 * e;
        smW[(gi >> 3) * 9 + (gi & 7)] = g_Wt4[gi];
    }
    __syncthreads();

    const int lane8 = tid & 7;       // role r
    const int tb = lane8 >> 1;       // basis-quartet owner
    const int tc = lane8 & 1;        // channel-octet owner
    const int pl = tid >> 3;         // point within block (0..31)
    const int n  = blockIdx.x * 32 + pl;

    const float NGL2 = -GAMMA * 1.4426950408889634f;
    float cs[4], K[4];
    #pragma unroll
    for (int bb = 0; bb < 4; bb++) {
        const float cb = __ldg(&centers[4 * tb + bb]);
        cs[bb] = -2.0f * NGL2 * cb;
        K[bb]  = NGL2 * cb * cb;
    }
    const float4 pc = g_coords4[n];

    unsigned long long acc2[4][4];   // [local basis][channel pair]
    #pragma unroll
    for (int bb = 0; bb < 4; bb++)
        #pragma unroll
        for (int cp = 0; cp < 4; cp++) acc2[bb][cp] = 0ull;

    const int*   nbp = neighbors + n * NNBR;
    const float* mkp = mask + n * NNBR;
    const ulonglong2* inT2 = (const ulonglong2*)g_inputT;

    #pragma unroll 4
    for (int k = 0; k < NNBR; k++) {
        const int   nbr = __ldg(&nbp[k]);      // broadcast within 8-lane group
        const float m   = __ldg(&mkp[k]);
        const float4 cc = g_coords4[nbr];
        const float dx = cc.x - pc.x;
        const float dy = cc.y - pc.y;
        const float dz = cc.z - pc.z;
        const float r2 = fmaf(dx, dx, fmaf(dy, dy, fmaf(dz, dz, EPSF)));
        const float r  = sqrt_approx(r2);
        const float e0 = fmaf(NGL2, r2, lg2(m));

        const ulonglong2 X0 = __ldg(&inT2[nbr * 4 + 2 * tc + 0]); // ch 8tc..8tc+3
        const ulonglong2 X1 = __ldg(&inT2[nbr * 4 + 2 * tc + 1]); // ch 8tc+4..8tc+7

        #pragma unroll
        for (int bb = 0; bb < 4; bb++) {
            const unsigned long long ud =
                dup2(ex2(fmaf(r, cs[bb], e0 + K[bb])));
            acc2[bb][0] = ffma2(ud, X0.x, acc2[bb][0]);
            acc2[bb][1] = ffma2(ud, X0.y, acc2[bb][1]);
            acc2[bb][2] = ffma2(ud, X1.x, acc2[bb][2]);
            acc2[bb][3] = ffma2(ud, X1.y, acc2[bb][3]);
        }
    }

    // Epilogue: s(o) = sum_{bb,hp} w(o,r,bb,hp) . acc2[bb][2hp..2hp+1]
    float po0 = 0.f, po1 = 0.f;
    #pragma unroll
    for (int o = 0; o < COUT; o++) {
        unsigned long long s2 = 0ull;
        const ulonglong2* grp = &smW[(o * 8 + lane8) * 9];
        #pragma unroll
        for (int bb = 0; bb < 4; bb++) {
            const ulonglong2 wa = grp[bb * 2 + 0];   // cp 0,1
            const ulonglong2 wb = grp[bb * 2 + 1];   // cp 2,3
            s2 = ffma2(wa.x, acc2[bb][0], s2);
            s2 = ffma2(wa.y, acc2[bb][1], s2);
            s2 = ffma2(wb.x, acc2[bb][2], s2);
            s2 = ffma2(wb.y, acc2[bb][3], s2);
        }
        const float2 sf = unpack2(s2);
        float s = sf.x + sf.y;
        s += __shfl_xor_sync(0xFFFFFFFFu, s, 1, 8);
        s += __shfl_xor_sync(0xFFFFFFFFu, s, 2, 8);
        s += __shfl_xor_sync(0xFFFFFFFFu, s, 4, 8);
        if ((o >> 1) == lane8) { if (o & 1) po1 = s; else po0 = s; }
    }

    out[(2 * lane8 + 0) * NPTS + n] = po0;
    out[(2 * lane8 + 1) * NPTS + n] = po1;
}

// ---------------------------------------------------------------------------
extern "C" void kernel_launch(void* const* d_in, const int* in_sizes, int n_in,
                              void* d_out, int out_size) {
    const float* input     = (const float*)d_in[0];   // (16, 16384)
    const float* coords    = (const float*)d_in[1];   // (16384, 3)
    const float* W         = (const float*)d_in[2];   // (16, 16, 16)
    const float* centers   = (const float*)d_in[3];   // (16,)
    const float* mask      = (const float*)d_in[4];   // (16384, 32)
    const int*   neighbors = (const int*)d_in[5];     // (16384, 32)
    float*       out       = (float*)d_out;           // (16, 16384)

    prep_kernel<<<128, 256>>>(input, coords, W);
    conv_kernel<<<NPTS / 32, 256>>>(centers, mask, neighbors, out);
}

// round 17
// speedup vs baseline: 2.1228x; 2.1228x over previous
#include <cuda_runtime.h>
#include <cuda_bf16.h>

#define NPTS  16384
#define NNBR  32
#define CIN   16
#define COUT  16
#define NB    16
#define GAMMA 10.0f
#define EPSF  1e-12f

// Scratch (allocation-free rule: __device__ globals)
__device__ float4     g_inputT[NPTS * 4];    // [n*4+q] : channels 4q..4q+3 of point n
__device__ float4     g_coords4[NPTS];       // padded coords
__device__ float2     g_re0[NPTS * NNBR];    // (r, e0=NGL2*r^2+log2(mask)) per (n,k), 4MB
__device__ ulonglong2 g_Wt3[1024];           // W tiled for 2x2-role epilogue (R15 layout):
// entry [(o*8 + j)*8 + tb*4 + c2] = ((W[o][4c2][8tb+j],W[o][4c2+1][8tb+j]),
//                                    (W[o][4c2+2][8tb+j],W[o][4c2+3][8tb+j]))

// ---------------- f32x2 / fast-math helpers (sm_103a) ----------------------
__device__ __forceinline__ unsigned long long ffma2(unsigned long long a,
                                                    unsigned long long b,
                                                    unsigned long long c) {
    unsigned long long d;
    asm("fma.rn.f32x2 %0, %1, %2, %3;" : "=l"(d) : "l"(a), "l"(b), "l"(c));
    return d;
}
__device__ __forceinline__ unsigned long long dup2(float x) {
    unsigned long long d;
    asm("mov.b64 %0, {%1, %1};" : "=l"(d) : "f"(x));
    return d;
}
__device__ __forceinline__ unsigned long long pack2(float lo, float hi) {
    unsigned long long d;
    asm("mov.b64 %0, {%1, %2};" : "=l"(d) : "f"(lo), "f"(hi));
    return d;
}
__device__ __forceinline__ float2 unpack2(unsigned long long v) {
    float2 f;
    asm("mov.b64 {%0, %1}, %2;" : "=f"(f.x), "=f"(f.y) : "l"(v));
    return f;
}
__device__ __forceinline__ float ex2(float x) {
    float y;
    asm("ex2.approx.ftz.f32 %0, %1;" : "=f"(y) : "f"(x));
    return y;
}
__device__ __forceinline__ float lg2(float x) {
    float y;
    asm("lg2.approx.ftz.f32 %0, %1;" : "=f"(y) : "f"(x));
    return y;
}
__device__ __forceinline__ float sqrt_approx(float x) {
    float y;
    asm("sqrt.approx.ftz.f32 %0, %1;" : "=f"(y) : "f"(x));
    return y;
}

// ---------------------------------------------------------------------------
// Prep: transpose input (C,N)->(N,C) float4 rows (2 pts/thread), pad coords,
// build the role-tiled W table (R15 layout, verified).
// ---------------------------------------------------------------------------
__global__ void prep_kernel(const float* __restrict__ input,
                            const float* __restrict__ coords,
                            const float* __restrict__ W) {
    const int idx = blockIdx.x * blockDim.x + threadIdx.x;   // 0 .. 32767
    const int q  = idx >> 13;           // 0..3 channel quartet
    const int n0 = (idx & 8191) * 2;    // even point index

    const float2* in2 = (const float2*)input;
    const float2 v0 = in2[((4 * q + 0) * NPTS + n0) >> 1];
    const float2 v1 = in2[((4 * q + 1) * NPTS + n0) >> 1];
    const float2 v2 = in2[((4 * q + 2) * NPTS + n0) >> 1];
    const float2 v3 = in2[((4 * q + 3) * NPTS + n0) >> 1];
    g_inputT[(n0 + 0) * 4 + q] = make_float4(v0.x, v1.x, v2.x, v3.x);
    g_inputT[(n0 + 1) * 4 + q] = make_float4(v0.y, v1.y, v2.y, v3.y);

    if (q == 0) {
        const float2* co2 = (const float2*)(coords + 3 * n0);   // 6 floats
        const float2 a = co2[0], b = co2[1], c = co2[2];
        g_coords4[n0 + 0] = make_float4(a.x, a.y, b.x, 0.0f);
        g_coords4[n0 + 1] = make_float4(b.y, c.x, c.y, 0.0f);
    }
    if (idx < 1024) {
        const int entry = idx & 7;       // tb*4 + c2
        const int tb = entry >> 2, c2 = entry & 3;
        const int row = idx >> 3;        // o*8 + j
        const int o = row >> 3, j = row & 7;
        const int b = 8 * tb + j;
        ulonglong2 w2;
        w2.x = pack2(W[(o * 16 + 4 * c2 + 0) * 16 + b], W[(o * 16 + 4 * c2 + 1) * 16 + b]);
        w2.y = pack2(W[(o * 16 + 4 * c2 + 2) * 16 + b], W[(o * 16 + 4 * c2 + 3) * 16 + b]);
        g_Wt3[idx] = w2;
    }
}

// ---------------------------------------------------------------------------
// Phase A (cheap, latency-tolerant): (r, e0) per (n,k). One thread per pair;
// all reads/writes coalesced except the single 16B coords gather.
// ---------------------------------------------------------------------------
__global__ __launch_bounds__(256)
void rphase_kernel(const float* __restrict__ mask,
                   const int*   __restrict__ neighbors) {
    const int idx = blockIdx.x * blockDim.x + threadIdx.x;   // 0 .. NPTS*NNBR-1
    const int n = idx >> 5;
    const float NGL2 = -GAMMA * 1.4426950408889634f;

    const int   nbr = __ldg(&neighbors[idx]);
    const float m   = __ldg(&mask[idx]);
    const float4 pc = g_coords4[n];
    const float4 cc = g_coords4[nbr];
    const float dx = cc.x - pc.x;
    const float dy = cc.y - pc.y;
    const float dz = cc.z - pc.z;
    const float r2 = fmaf(dx, dx, fmaf(dy, dy, fmaf(dz, dz, EPSF)));
    const float r  = sqrt_approx(r2);
    const float e0 = fmaf(NGL2, r2, lg2(m));
    g_re0[idx] = make_float2(r, e0);
}

// ---------------------------------------------------------------------------
// Main: 4 lanes/point, 2x2 tile (tb,tc): bases 8tb..8tb+7 x channels
// 8tc..8tc+7 (R15 structure, measured best). Mainloop L1 diet:
//  - (r,e0) staged in smem (stride 68 floats -> conflict-free LDS across pts)
//  - neighbor indices int4 per quad
//  - 2 X LDG.128 per nbr per lane (unchanged)
//  - no coords / mask / sqrt / lg2 in the loop; MUFU = 8 ex2 per nbr only.
// Epilogue: R15 verbatim (role-tiled W smem, width-4 butterfly).
// ---------------------------------------------------------------------------
__global__ __launch_bounds__(256, 2)
void conv_kernel(const float* __restrict__ centers,
                 const int*   __restrict__ neighbors,
                 float*       __restrict__ out) {
    __shared__ ulonglong2 smW3[1024];    // 16KB
    __shared__ float      sre0[64 * 68]; // 17408B, stride 68 floats per point

    const int tid = threadIdx.x;
    #pragma unroll
    for (int e = 0; e < 4; e++)
        smW3[tid + 256 * e] = g_Wt3[tid + 256 * e];
    // Stage (r,e0) slab: 64 pts x 16 float4, contiguous in g_re0.
    {
        const float4* slab = (const float4*)(g_re0 + blockIdx.x * (64 * NNBR));
        float4* s4 = (float4*)sre0;
        #pragma unroll
        for (int e = 0; e < 4; e++) {
            const int gi = tid + 256 * e;        // 0..1023
            const int pt = gi >> 4;
            const int w  = gi & 15;
            s4[pt * 17 + w] = slab[gi];          // 17 float4 = 68 floats per pt
        }
    }
    __syncthreads();

    const int t  = tid & 3;
    const int tb = t >> 1;           // basis-octet owner
    const int tc = t & 1;            // channel-octet owner
    const int pl = tid >> 2;         // point within block (0..63)
    const int n  = blockIdx.x * 64 + pl;

    const float NGL2 = -GAMMA * 1.4426950408889634f;
    float cs[8], K[8];
    #pragma unroll
    for (int bb = 0; bb < 8; bb++) {
        const float cb = __ldg(&centers[8 * tb + bb]);
        cs[bb] = -2.0f * NGL2 * cb;
        K[bb]  = NGL2 * cb * cb;
    }

    unsigned long long acc2[8][4];   // [local basis][channel pair]
    #pragma unroll
    for (int bb = 0; bb < 8; bb++)
        #pragma unroll
        for (int cp = 0; cp < 4; cp++) acc2[bb][cp] = 0ull;

    const int4* nb4 = (const int4*)(neighbors + n * NNBR);
    const ulonglong2* inT2 = (const ulonglong2*)g_inputT;
    const float* myre0 = sre0 + pl * 68;

    #pragma unroll 2
    for (int kk = 0; kk < 8; kk++) {
        const int4 nb = __ldg(&nb4[kk]);
        // (r,e0) for the 4 nbrs of this quad: 2 conflict-free LDS.128
        const ulonglong2 ra = *(const ulonglong2*)(myre0 + 8 * kk);      // nbrs 0,1
        const ulonglong2 rb = *(const ulonglong2*)(myre0 + 8 * kk + 4);  // nbrs 2,3
        const int ns[4] = {nb.x, nb.y, nb.z, nb.w};
        const float2 res[4] = {unpack2(ra.x), unpack2(ra.y),
                               unpack2(rb.x), unpack2(rb.y)};

        #pragma unroll
        for (int j = 0; j < 4; j++) {
            const int   nbr = ns[j];
            const float r   = res[j].x;
            const float e0  = res[j].y;
            const ulonglong2 X0 = __ldg(&inT2[nbr * 4 + 2 * tc + 0]); // ch 8tc..+3
            const ulonglong2 X1 = __ldg(&inT2[nbr * 4 + 2 * tc + 1]); // ch 8tc+4..+7

            #pragma unroll
            for (int bb = 0; bb < 8; bb++) {
                const unsigned long long ud =
                    dup2(ex2(fmaf(r, cs[bb], e0 + K[bb])));
                acc2[bb][0] = ffma2(ud, X0.x, acc2[bb][0]);
                acc2[bb][1] = ffma2(ud, X0.y, acc2[bb][1]);
                acc2[bb][2] = ffma2(ud, X1.x, acc2[bb][2]);
                acc2[bb][3] = ffma2(ud, X1.y, acc2[bb][3]);
            }
        }
    }

    // Epilogue (R15 verbatim): s(o) = sum_{bb,cp} W3[o][bb][role] . acc2[bb][cp]
    float po[4];
    #pragma unroll
    for (int o = 0; o < COUT; o++) {
        unsigned long long s2 = 0ull;
        #pragma unroll
        for (int bb = 0; bb < 8; bb++) {
            const ulonglong2* rowp = &smW3[(o * 8 + bb) * 8 + tb * 4 + 2 * tc];
            const ulonglong2 wa = rowp[0];   // channel pairs 0,1
            const ulonglong2 wb = rowp[1];   // channel pairs 2,3
            s2 = ffma2(wa.x, acc2[bb][0], s2);
            s2 = ffma2(wa.y, acc2[bb][1], s2);
            s2 = ffma2(wb.x, acc2[bb][2], s2);
            s2 = ffma2(wb.y, acc2[bb][3], s2);
        }
        const float2 sf = unpack2(s2);
        float s = sf.x + sf.y;
        s += __shfl_xor_sync(0xFFFFFFFFu, s, 1, 4);
        s += __shfl_xor_sync(0xFFFFFFFFu, s, 2, 4);
        if ((o >> 2) == t) po[o & 3] = s;
    }

    #pragma unroll
    for (int j = 0; j < 4; j++)
        out[(4 * t + j) * NPTS + n] = po[j];
}

// ---------------------------------------------------------------------------
extern "C" void kernel_launch(void* const* d_in, const int* in_sizes, int n_in,
                              void* d_out, int out_size) {
    const float* input     = (const float*)d_in[0];   // (16, 16384)
    const float* coords    = (const float*)d_in[1];   // (16384, 3)
    const float* W         = (const float*)d_in[2];   // (16, 16, 16)
    const float* centers   = (const float*)d_in[3];   // (16,)
    const float* mask      = (const float*)d_in[4];   // (16384, 32)
    const int*   neighbors = (const int*)d_in[5];     // (16384, 32)
    float*       out       = (float*)d_out;           // (16, 16384)

    prep_kernel<<<128, 256>>>(input, coords, W);
    rphase_kernel<<<(NPTS * NNBR) / 256, 256>>>(mask, neighbors);
    conv_kernel<<<NPTS / 64, 256>>>(centers, neighbors, out);
}